// round 15
// baseline (speedup 1.0000x reference)
#include <cuda_runtime.h>
#include <cuda_bf16.h>

#define NN 100000
#define DD 64
#define EMAX 1000000
#define SCAN_CHUNK 512   // blocks = ceil(NN/512) = 196 <= 256

typedef unsigned long long u64;

// ---------------- f32x2 packed math (Blackwell sm_103a) ----------------
__device__ __forceinline__ u64 fma2(u64 a, u64 b, u64 c) {
    u64 d;
    asm("fma.rn.f32x2 %0, %1, %2, %3;" : "=l"(d) : "l"(a), "l"(b), "l"(c));
    return d;
}
__device__ __forceinline__ u64 add2(u64 a, u64 b) {
    u64 d;
    asm("add.rn.f32x2 %0, %1, %2;" : "=l"(d) : "l"(a), "l"(b));
    return d;
}
__device__ __forceinline__ u64 mul2(u64 a, u64 b) {
    u64 d;
    asm("mul.rn.f32x2 %0, %1, %2;" : "=l"(d) : "l"(a), "l"(b));
    return d;
}
__device__ __forceinline__ float lo32(u64 a) { return __uint_as_float((unsigned)a); }
__device__ __forceinline__ float hi32(u64 a) { return __uint_as_float((unsigned)(a >> 32)); }

// ---------------- device scratch (no allocation allowed) ----------------
__device__ float g_h1[NN * DD];
__device__ float g_hout[NN * DD];
__device__ float g_p[NN * DD];
__device__ float g_q[NN * DD];
__device__ float g_Wpl[DD * DD];
__device__ float g_Wqr[DD * DD];
__device__ float g_bp[DD];
__device__ float g_bq[DD];
__device__ float g_bzero[DD];        // never written: stays zero
__device__ int   g_deg[NN];          // zero at entry: loader-init, then k_scan restores
__device__ int   g_rowptr[NN + 1];
__device__ int   g_cursor[NN];
__device__ int   g_col[EMAX];
__device__ u64   g_scan_state[256];  // zeroed by k_hist each launch (before k_scan)

// ---------------- weight composition (layer 1 folded through node_lin) ----------------
// Wpl = Wl1 @ W_lin ; Wqr = Wr1 @ W_lin
// bp = Wl1 @ b_lin ; bq = bl1 + Wr1 @ b_lin
__global__ void k_compose(const float* __restrict__ W_lin, const float* __restrict__ b_lin,
                          const float* __restrict__ Wl1, const float* __restrict__ bl1,
                          const float* __restrict__ Wr1,
                          float* __restrict__ Wpl, float* __restrict__ Wqr,
                          float* __restrict__ bp, float* __restrict__ bq) {
    int t = threadIdx.x;          // 256 threads
    int i = t >> 2;               // output row 0..63
    int j0 = (t & 3) * 16;        // 16 output cols per thread
    for (int j = j0; j < j0 + 16; j++) {
        float a = 0.f, b = 0.f;
        for (int k = 0; k < DD; k++) {
            float w = W_lin[k * DD + j];
            a += Wl1[i * DD + k] * w;
            b += Wr1[i * DD + k] * w;
        }
        Wpl[i * DD + j] = a;
        Wqr[i * DD + j] = b;
    }
    if ((t & 3) == 0) {
        float a = 0.f, b = 0.f;
        for (int k = 0; k < DD; k++) {
            a += Wl1[i * DD + k] * b_lin[k];
            b += Wr1[i * DD + k] * b_lin[k];
        }
        bp[i] = a;
        bq[i] = bl1[i] + b;
    }
}

// ---------------- histogram (int4 vectorized; also zeroes scan state) ----------------
__global__ void k_hist(const int* __restrict__ dst, int* __restrict__ deg,
                       u64* __restrict__ state, int E) {
    int i = blockIdx.x * blockDim.x + threadIdx.x;
    int stride = gridDim.x * blockDim.x;
    if (i < 256) state[i] = 0ULL;        // reset for k_scan (runs strictly after)
    if ((((size_t)dst) & 15) == 0) {
        int E4 = E >> 2;
        for (int k = i; k < E4; k += stride) {
            int4 d = ((const int4*)dst)[k];
            atomicAdd(&deg[d.x], 1);
            atomicAdd(&deg[d.y], 1);
            atomicAdd(&deg[d.z], 1);
            atomicAdd(&deg[d.w], 1);
        }
        for (int e = (E4 << 2) + i; e < E; e += stride)
            atomicAdd(&deg[dst[e]], 1);
    } else {
        for (int e = i; e < E; e += stride)
            atomicAdd(&deg[dst[e]], 1);
    }
}

// single-pass decoupled-lookback exclusive scan: deg -> rowptr/cursor.
// Self-zeroes deg after reading (restores the deg==0 launch invariant).
__global__ void k_scan(int* __restrict__ deg, int* __restrict__ rowptr,
                       int* __restrict__ cursor, u64* __restrict__ state,
                       int n, int nblk) {
    __shared__ int ps[256];
    __shared__ int s_ex;
    int b = blockIdx.x;
    int t = threadIdx.x;
    int base = b * SCAN_CHUNK + t * 2;
    int d0 = 0, d1 = 0;
    if (base < n)     { d0 = deg[base];     deg[base] = 0; }
    if (base + 1 < n) { d1 = deg[base + 1]; deg[base + 1] = 0; }
    ps[t] = d0 + d1;
    __syncthreads();
    for (int d = 1; d < 256; d <<= 1) {
        int v = (t >= d) ? ps[t - d] : 0;
        __syncthreads();
        ps[t] += v;
        __syncthreads();
    }
    int total = ps[255];

    if (t == 0) {
        if (b == 0) {
            atomicExch(&state[0], ((u64)total << 2) | 2ULL);
            s_ex = 0;
        } else {
            atomicExch(&state[b], ((u64)total << 2) | 1ULL);
            int ex = 0;
            int p = b - 1;
            while (true) {
                u64 s;
                do {
                    s = *(volatile u64*)&state[p];
                } while ((s & 3ULL) == 0ULL);
                int v = (int)(s >> 2);
                ex += v;
                if ((s & 3ULL) == 2ULL) break;
                p--;
            }
            atomicExch(&state[b], ((u64)(ex + total) << 2) | 2ULL);
            s_ex = ex;
        }
    }
    __syncthreads();
    int off = s_ex + ps[t] - (d0 + d1);
    if (base < n)     { rowptr[base] = off;          cursor[base] = off; }
    if (base + 1 < n) { rowptr[base + 1] = off + d0; cursor[base + 1] = off + d0; }
    if (b == nblk - 1 && t == 255) rowptr[n] = s_ex + total;
}

__global__ void k_scatter(const int* __restrict__ src, const int* __restrict__ dst,
                          int* __restrict__ cursor, int* __restrict__ col, int E) {
    for (int e = blockIdx.x * blockDim.x + threadIdx.x; e < E; e += gridDim.x * blockDim.x) {
        int d = dst[e];
        int p = atomicAdd(&cursor[d], 1);
        col[p] = src[e];
    }
}

// ---------------- fused mean-aggregate + combine (proven round-10 shape) ----------------
// out[i] = act( mean_{j in N(i)} p[j]  +  q[i] )
__global__ __launch_bounds__(256) void k_aggc(
    const float* __restrict__ p, const float* __restrict__ q,
    const int* __restrict__ rowptr, const int* __restrict__ col,
    float* __restrict__ out, int n, int do_relu) {
    int node = (blockIdx.x * blockDim.x + threadIdx.x) >> 4;
    int l = threadIdx.x & 15;
    if (node >= n) return;
    int s = rowptr[node];
    int e = rowptr[node + 1];
    u64 axy = 0ULL, azw = 0ULL;
    int nn = s;
    for (; nn + 8 <= e; nn += 8) {
        int c0 = col[nn],     c1 = col[nn + 1], c2 = col[nn + 2], c3 = col[nn + 3];
        int c4 = col[nn + 4], c5 = col[nn + 5], c6 = col[nn + 6], c7 = col[nn + 7];
        ulonglong2 v0 = ((const ulonglong2*)(p + c0 * DD))[l];
        ulonglong2 v1 = ((const ulonglong2*)(p + c1 * DD))[l];
        ulonglong2 v2 = ((const ulonglong2*)(p + c2 * DD))[l];
        ulonglong2 v3 = ((const ulonglong2*)(p + c3 * DD))[l];
        ulonglong2 v4 = ((const ulonglong2*)(p + c4 * DD))[l];
        ulonglong2 v5 = ((const ulonglong2*)(p + c5 * DD))[l];
        ulonglong2 v6 = ((const ulonglong2*)(p + c6 * DD))[l];
        ulonglong2 v7 = ((const ulonglong2*)(p + c7 * DD))[l];
        u64 p0 = add2(add2(v0.x, v1.x), add2(v2.x, v3.x));
        u64 p1 = add2(add2(v4.x, v5.x), add2(v6.x, v7.x));
        u64 q0 = add2(add2(v0.y, v1.y), add2(v2.y, v3.y));
        u64 q1 = add2(add2(v4.y, v5.y), add2(v6.y, v7.y));
        axy = add2(axy, add2(p0, p1));
        azw = add2(azw, add2(q0, q1));
    }
    for (; nn + 4 <= e; nn += 4) {
        int c0 = col[nn], c1 = col[nn + 1], c2 = col[nn + 2], c3 = col[nn + 3];
        ulonglong2 v0 = ((const ulonglong2*)(p + c0 * DD))[l];
        ulonglong2 v1 = ((const ulonglong2*)(p + c1 * DD))[l];
        ulonglong2 v2 = ((const ulonglong2*)(p + c2 * DD))[l];
        ulonglong2 v3 = ((const ulonglong2*)(p + c3 * DD))[l];
        axy = add2(axy, add2(add2(v0.x, v1.x), add2(v2.x, v3.x)));
        azw = add2(azw, add2(add2(v0.y, v1.y), add2(v2.y, v3.y)));
    }
    for (; nn < e; nn++) {
        ulonglong2 v = ((const ulonglong2*)(p + col[nn] * DD))[l];
        axy = add2(axy, v.x);
        azw = add2(azw, v.y);
    }
    float inv = (e > s) ? 1.f / (float)(e - s) : 0.f;
    unsigned ui = __float_as_uint(inv);
    u64 inv2 = ((u64)ui << 32) | ui;
    ulonglong2 qv = ((const ulonglong2*)(q + node * DD))[l];
    u64 rxy = add2(mul2(axy, inv2), qv.x);
    u64 rzw = add2(mul2(azw, inv2), qv.y);
    if (do_relu) {
        float x0 = fmaxf(lo32(rxy), 0.f), x1 = fmaxf(hi32(rxy), 0.f);
        float x2 = fmaxf(lo32(rzw), 0.f), x3 = fmaxf(hi32(rzw), 0.f);
        rxy = ((u64)__float_as_uint(x1) << 32) | __float_as_uint(x0);
        rzw = ((u64)__float_as_uint(x3) << 32) | __float_as_uint(x2);
    }
    ((ulonglong2*)(out + node * DD))[l] = make_ulonglong2(rxy, rzw);
}

// ---------------- dual-output transform: p = h@Wl^T + bp, q = h@Wr^T + bq ----------------
// 8 nodes per block-iteration; each thread computes col j for 2 nodes.
__global__ __launch_bounds__(256, 1) void k_gemmPQ(
    const float* __restrict__ h,
    const float* __restrict__ Wl, const float* __restrict__ Wr,
    const float* __restrict__ bp, const float* __restrict__ bq,
    float* __restrict__ p, float* __restrict__ q, int n) {
    __shared__ __align__(16) float sh[2][8][DD];
    int tid = threadIdx.x;
    int g = tid >> 6;       // 0..3
    int j = tid & 63;

    u64 wl2[32], wr2[32];
#pragma unroll
    for (int k = 0; k < 32; k += 2) {
        ulonglong2 a = *(const ulonglong2*)&Wl[j * DD + k * 2];
        wl2[k] = a.x; wl2[k + 1] = a.y;
        ulonglong2 c = *(const ulonglong2*)&Wr[j * DD + k * 2];
        wr2[k] = c.x; wr2[k + 1] = c.y;
    }
    float bpj = bp[j];
    float bqj = bq[j];

    int stride = gridDim.x * 8;
    int iA0 = blockIdx.x * 8 + g;
    int iB0 = iA0 + 4;
    float hvA = (iA0 < n) ? h[iA0 * DD + j] : 0.f;
    float hvB = (iB0 < n) ? h[iB0 * DD + j] : 0.f;
    int buf = 0;
    for (int base = blockIdx.x * 8; base < n; base += stride) {
        int iA = base + g;
        int iB = iA + 4;
        sh[buf][g][j] = hvA;
        sh[buf][g + 4][j] = hvB;
        __syncthreads();
        int nA = iA + stride, nB = iB + stride;
        hvA = (nA < n) ? h[nA * DD + j] : 0.f;
        hvB = (nB < n) ? h[nB * DD + j] : 0.f;

        const ulonglong2* hA = (const ulonglong2*)sh[buf][g];
        const ulonglong2* hB = (const ulonglong2*)sh[buf][g + 4];
        u64 pA0 = 0ULL, pA1 = 0ULL, qA0 = 0ULL, qA1 = 0ULL;
        u64 pB0 = 0ULL, pB1 = 0ULL, qB0 = 0ULL, qB1 = 0ULL;
#pragma unroll
        for (int k4 = 0; k4 < 16; k4++) {
            ulonglong2 Ha = hA[k4];
            ulonglong2 Hb = hB[k4];
            u64 wlo = wl2[2 * k4], whi = wl2[2 * k4 + 1];
            u64 rlo = wr2[2 * k4], rhi = wr2[2 * k4 + 1];
            pA0 = fma2(Ha.x, wlo, pA0);
            pA1 = fma2(Ha.y, whi, pA1);
            qA0 = fma2(Ha.x, rlo, qA0);
            qA1 = fma2(Ha.y, rhi, qA1);
            pB0 = fma2(Hb.x, wlo, pB0);
            pB1 = fma2(Hb.y, whi, pB1);
            qB0 = fma2(Hb.x, rlo, qB0);
            qB1 = fma2(Hb.y, rhi, qB1);
        }
        if (iA < n) {
            p[iA * DD + j] = (lo32(pA0) + hi32(pA0)) + (lo32(pA1) + hi32(pA1)) + bpj;
            q[iA * DD + j] = (lo32(qA0) + hi32(qA0)) + (lo32(qA1) + hi32(qA1)) + bqj;
        }
        if (iB < n) {
            p[iB * DD + j] = (lo32(pB0) + hi32(pB0)) + (lo32(pB1) + hi32(pB1)) + bpj;
            q[iB * DD + j] = (lo32(qB0) + hi32(qB0)) + (lo32(qB1) + hi32(qB1)) + bqj;
        }
        buf ^= 1;
        __syncthreads();
    }
}

// ---------------- edge dot product (warp per edge, f32x2 lanes) ----------------
__global__ __launch_bounds__(256) void k_edge(
    const float* __restrict__ h, const int* __restrict__ ea,
    const int* __restrict__ eb, float* __restrict__ out, int E) {
    int w = (blockIdx.x * blockDim.x + threadIdx.x) >> 5;
    int lane = threadIdx.x & 31;
    if (w >= E) return;
    int a = ea[w];
    int b = eb[w];
    ulonglong2 va = ((const ulonglong2*)(h + a * DD))[lane >> 1];
    ulonglong2 vb = ((const ulonglong2*)(h + b * DD))[lane >> 1];
    u64 acc = mul2((lane & 1) ? va.y : va.x, (lane & 1) ? vb.y : vb.x);
    float p = lo32(acc) + hi32(acc);
#pragma unroll
    for (int o = 16; o > 0; o >>= 1) p += __shfl_down_sync(0xffffffffu, p, o);
    if (lane == 0) out[w] = p;
}

// ---------------- launch ----------------
static cudaStream_t s_side = nullptr;
static cudaEvent_t  s_evF = nullptr;
static cudaEvent_t  s_evPQ = nullptr;

extern "C" void kernel_launch(void* const* d_in, const int* in_sizes, int n_in,
                              void* d_out, int out_size) {
    const float* x     = (const float*)d_in[0];
    const int*   ei    = (const int*)d_in[1];
    const int*   eli   = (const int*)d_in[2];
    const float* W_lin = (const float*)d_in[3];
    const float* b_lin = (const float*)d_in[4];
    const float* Wl1   = (const float*)d_in[5];
    const float* bl1   = (const float*)d_in[6];
    const float* Wr1   = (const float*)d_in[7];
    const float* Wl2   = (const float*)d_in[8];
    const float* bl2   = (const float*)d_in[9];
    const float* Wr2   = (const float*)d_in[10];

    int N  = in_sizes[0] / DD;      // 100000
    int E  = in_sizes[1] / 2;       // 1000000
    int EL = in_sizes[2] / 2;       // 200000

    const int* src = ei;            // edge_index[0] = source
    const int* dst = ei + E;        // edge_index[1] = target
    const int* ea  = eli;
    const int* eb  = eli + EL;

    float *h1, *hout, *p, *q, *Wpl, *Wqr, *bp, *bq, *bzero;
    int *deg, *rowptr, *cursor, *col;
    u64 *state;
    cudaGetSymbolAddress((void**)&h1, g_h1);
    cudaGetSymbolAddress((void**)&hout, g_hout);
    cudaGetSymbolAddress((void**)&p, g_p);
    cudaGetSymbolAddress((void**)&q, g_q);
    cudaGetSymbolAddress((void**)&Wpl, g_Wpl);
    cudaGetSymbolAddress((void**)&Wqr, g_Wqr);
    cudaGetSymbolAddress((void**)&bp, g_bp);
    cudaGetSymbolAddress((void**)&bq, g_bq);
    cudaGetSymbolAddress((void**)&bzero, g_bzero);
    cudaGetSymbolAddress((void**)&deg, g_deg);
    cudaGetSymbolAddress((void**)&rowptr, g_rowptr);
    cudaGetSymbolAddress((void**)&cursor, g_cursor);
    cudaGetSymbolAddress((void**)&col, g_col);
    cudaGetSymbolAddress((void**)&state, g_scan_state);

    float* preds = (float*)d_out;

    // One-time stream/event creation (first call is the uncaptured correctness
    // run, so no resource creation happens during graph capture).
    if (s_side == nullptr) {
        cudaStreamCreateWithFlags(&s_side, cudaStreamNonBlocking);
        cudaEventCreateWithFlags(&s_evF, cudaEventDisableTiming);
        cudaEventCreateWithFlags(&s_evPQ, cudaEventDisableTiming);
    }

    int nblk = (N + SCAN_CHUNK - 1) / SCAN_CHUNK;   // 196 <= 256

    // Side stream: compose layer-1 weights through node_lin, then directly
    // compute p,q from x. Fully overlapped with the CSR build.
    cudaEventRecord(s_evF, 0);
    cudaStreamWaitEvent(s_side, s_evF, 0);
    k_compose<<<1, 256, 0, s_side>>>(W_lin, b_lin, Wl1, bl1, Wr1, Wpl, Wqr, bp, bq);
    k_gemmPQ<<<148, 256, 0, s_side>>>(x, Wpl, Wqr, bp, bq, p, q, N);
    cudaEventRecord(s_evPQ, s_side);

    // Main stream: CSR build (no memset nodes — k_hist zeroes scan state,
    // k_scan restores deg==0 for the next replay).
    k_hist<<<1024, 256>>>(dst, deg, state, E);
    k_scan<<<nblk, 256>>>(deg, rowptr, cursor, state, N, nblk);
    k_scatter<<<2048, 256>>>(src, dst, cursor, col, E);

    // Join: aggregation needs p,q and CSR.
    cudaStreamWaitEvent(0, s_evPQ, 0);

    int agg_blocks = (N * 16 + 255) / 256;

    // layer 1: h1 = relu(agg(p) + q)
    k_aggc<<<agg_blocks, 256>>>(p, q, rowptr, col, h1, N, 1);
    // layer 2 transform: p,q from h1
    k_gemmPQ<<<148, 256>>>(h1, Wl2, Wr2, bzero, bl2, p, q, N);
    // layer 2 combine: hout = agg(p) + q
    k_aggc<<<agg_blocks, 256>>>(p, q, rowptr, col, hout, N, 0);

    // edge classifier
    int blocks = (EL * 32 + 255) / 256;
    k_edge<<<blocks, 256>>>(hout, ea, eb, preds, EL);
}

// round 17
// speedup vs baseline: 1.2179x; 1.2179x over previous
#include <cuda_runtime.h>
#include <cuda_bf16.h>

#define NN 100000
#define DD 64
#define EMAX 1000000
#define SCAN_CHUNK 512   // blocks = ceil(NN/512) = 196 <= 256

typedef unsigned long long u64;

// ---------------- f32x2 packed math (Blackwell sm_103a) ----------------
__device__ __forceinline__ u64 fma2(u64 a, u64 b, u64 c) {
    u64 d;
    asm("fma.rn.f32x2 %0, %1, %2, %3;" : "=l"(d) : "l"(a), "l"(b), "l"(c));
    return d;
}
__device__ __forceinline__ u64 add2(u64 a, u64 b) {
    u64 d;
    asm("add.rn.f32x2 %0, %1, %2;" : "=l"(d) : "l"(a), "l"(b));
    return d;
}
__device__ __forceinline__ u64 mul2(u64 a, u64 b) {
    u64 d;
    asm("mul.rn.f32x2 %0, %1, %2;" : "=l"(d) : "l"(a), "l"(b));
    return d;
}
__device__ __forceinline__ float lo32(u64 a) { return __uint_as_float((unsigned)a); }
__device__ __forceinline__ float hi32(u64 a) { return __uint_as_float((unsigned)(a >> 32)); }

// ---------------- PDL primitives (sm_90+; no-ops without PDL launch) ----------------
__device__ __forceinline__ void gdep_wait() {
    asm volatile("griddepcontrol.wait;" ::: "memory");
}
__device__ __forceinline__ void gdep_launch_dependents() {
    asm volatile("griddepcontrol.launch_dependents;" ::: "memory");
}

// ---------------- device scratch (no allocation allowed) ----------------
__device__ float g_h0[NN * DD];
__device__ float g_h1[NN * DD];
__device__ float g_p[NN * DD];
__device__ float g_q[NN * DD];
__device__ int   g_deg[NN];
__device__ int   g_rowptr[NN + 1];
__device__ int   g_cursor[NN];
__device__ int   g_col[EMAX];
__device__ u64   g_scan_state[256];   // memset to 0 each launch

// ---------------- histogram (int4 vectorized) ----------------
__global__ void k_hist(const int* __restrict__ dst, int* __restrict__ deg, int E) {
    int i = blockIdx.x * blockDim.x + threadIdx.x;
    int stride = gridDim.x * blockDim.x;
    if ((((size_t)dst) & 15) == 0) {
        int E4 = E >> 2;
        for (int k = i; k < E4; k += stride) {
            int4 d = ((const int4*)dst)[k];
            atomicAdd(&deg[d.x], 1);
            atomicAdd(&deg[d.y], 1);
            atomicAdd(&deg[d.z], 1);
            atomicAdd(&deg[d.w], 1);
        }
        for (int e = (E4 << 2) + i; e < E; e += stride)
            atomicAdd(&deg[dst[e]], 1);
    } else {
        for (int e = i; e < E; e += stride)
            atomicAdd(&deg[dst[e]], 1);
    }
    gdep_launch_dependents();
}

// single-pass decoupled-lookback exclusive scan: deg -> rowptr/cursor
__global__ void k_scan(const int* __restrict__ deg, int* __restrict__ rowptr,
                       int* __restrict__ cursor, u64* __restrict__ state,
                       int n, int nblk) {
    __shared__ int ps[256];
    __shared__ int s_ex;
    gdep_wait();
    int b = blockIdx.x;
    int t = threadIdx.x;
    int base = b * SCAN_CHUNK + t * 2;
    int d0 = (base < n) ? deg[base] : 0;
    int d1 = (base + 1 < n) ? deg[base + 1] : 0;
    ps[t] = d0 + d1;
    __syncthreads();
    for (int d = 1; d < 256; d <<= 1) {
        int v = (t >= d) ? ps[t - d] : 0;
        __syncthreads();
        ps[t] += v;
        __syncthreads();
    }
    int total = ps[255];

    if (t == 0) {
        if (b == 0) {
            atomicExch(&state[0], ((u64)total << 2) | 2ULL);
            s_ex = 0;
        } else {
            atomicExch(&state[b], ((u64)total << 2) | 1ULL);
            int ex = 0;
            int p = b - 1;
            while (true) {
                u64 s;
                do {
                    s = *(volatile u64*)&state[p];
                } while ((s & 3ULL) == 0ULL);
                int v = (int)(s >> 2);
                ex += v;
                if ((s & 3ULL) == 2ULL) break;
                p--;
            }
            atomicExch(&state[b], ((u64)(ex + total) << 2) | 2ULL);
            s_ex = ex;
        }
    }
    __syncthreads();
    int off = s_ex + ps[t] - (d0 + d1);
    if (base < n)     { rowptr[base] = off;          cursor[base] = off; }
    if (base + 1 < n) { rowptr[base + 1] = off + d0; cursor[base + 1] = off + d0; }
    if (b == nblk - 1 && t == 255) rowptr[n] = s_ex + total;
    gdep_launch_dependents();
}

__global__ void k_scatter(const int* __restrict__ src, const int* __restrict__ dst,
                          int* __restrict__ cursor, int* __restrict__ col, int E) {
    gdep_wait();
    for (int e = blockIdx.x * blockDim.x + threadIdx.x; e < E; e += gridDim.x * blockDim.x) {
        int d = dst[e];
        int p = atomicAdd(&cursor[d], 1);
        col[p] = src[e];
    }
    gdep_launch_dependents();
}

// ---------------- fused mean-aggregate + combine (proven round-10 shape) ----------------
// out[i] = act( mean_{j in N(i)} p[j]  +  q[i] )
__global__ __launch_bounds__(256) void k_aggc(
    const float* __restrict__ p, const float* __restrict__ q,
    const int* __restrict__ rowptr, const int* __restrict__ col,
    float* __restrict__ out, int n, int do_relu) {
    gdep_wait();
    int node = (blockIdx.x * blockDim.x + threadIdx.x) >> 4;
    int l = threadIdx.x & 15;
    if (node >= n) { gdep_launch_dependents(); return; }
    int s = rowptr[node];
    int e = rowptr[node + 1];
    u64 axy = 0ULL, azw = 0ULL;
    int nn = s;
    for (; nn + 8 <= e; nn += 8) {
        int c0 = col[nn],     c1 = col[nn + 1], c2 = col[nn + 2], c3 = col[nn + 3];
        int c4 = col[nn + 4], c5 = col[nn + 5], c6 = col[nn + 6], c7 = col[nn + 7];
        ulonglong2 v0 = ((const ulonglong2*)(p + c0 * DD))[l];
        ulonglong2 v1 = ((const ulonglong2*)(p + c1 * DD))[l];
        ulonglong2 v2 = ((const ulonglong2*)(p + c2 * DD))[l];
        ulonglong2 v3 = ((const ulonglong2*)(p + c3 * DD))[l];
        ulonglong2 v4 = ((const ulonglong2*)(p + c4 * DD))[l];
        ulonglong2 v5 = ((const ulonglong2*)(p + c5 * DD))[l];
        ulonglong2 v6 = ((const ulonglong2*)(p + c6 * DD))[l];
        ulonglong2 v7 = ((const ulonglong2*)(p + c7 * DD))[l];
        u64 p0 = add2(add2(v0.x, v1.x), add2(v2.x, v3.x));
        u64 p1 = add2(add2(v4.x, v5.x), add2(v6.x, v7.x));
        u64 q0 = add2(add2(v0.y, v1.y), add2(v2.y, v3.y));
        u64 q1 = add2(add2(v4.y, v5.y), add2(v6.y, v7.y));
        axy = add2(axy, add2(p0, p1));
        azw = add2(azw, add2(q0, q1));
    }
    for (; nn + 4 <= e; nn += 4) {
        int c0 = col[nn], c1 = col[nn + 1], c2 = col[nn + 2], c3 = col[nn + 3];
        ulonglong2 v0 = ((const ulonglong2*)(p + c0 * DD))[l];
        ulonglong2 v1 = ((const ulonglong2*)(p + c1 * DD))[l];
        ulonglong2 v2 = ((const ulonglong2*)(p + c2 * DD))[l];
        ulonglong2 v3 = ((const ulonglong2*)(p + c3 * DD))[l];
        axy = add2(axy, add2(add2(v0.x, v1.x), add2(v2.x, v3.x)));
        azw = add2(azw, add2(add2(v0.y, v1.y), add2(v2.y, v3.y)));
    }
    for (; nn < e; nn++) {
        ulonglong2 v = ((const ulonglong2*)(p + col[nn] * DD))[l];
        axy = add2(axy, v.x);
        azw = add2(azw, v.y);
    }
    float inv = (e > s) ? 1.f / (float)(e - s) : 0.f;
    unsigned ui = __float_as_uint(inv);
    u64 inv2 = ((u64)ui << 32) | ui;
    ulonglong2 qv = ((const ulonglong2*)(q + node * DD))[l];
    u64 rxy = add2(mul2(axy, inv2), qv.x);
    u64 rzw = add2(mul2(azw, inv2), qv.y);
    if (do_relu) {
        float x0 = fmaxf(lo32(rxy), 0.f), x1 = fmaxf(hi32(rxy), 0.f);
        float x2 = fmaxf(lo32(rzw), 0.f), x3 = fmaxf(hi32(rzw), 0.f);
        rxy = ((u64)__float_as_uint(x1) << 32) | __float_as_uint(x0);
        rzw = ((u64)__float_as_uint(x3) << 32) | __float_as_uint(x2);
    }
    ((ulonglong2*)(out + node * DD))[l] = make_ulonglong2(rxy, rzw);
    gdep_launch_dependents();
}

// ---------------- node linear: out = x @ W^T + b (f32x2, double-buffered) ----------------
__global__ __launch_bounds__(256, 2) void k_lin(
    const float* __restrict__ x, const float* __restrict__ W,
    const float* __restrict__ b, float* __restrict__ out, int n) {
    __shared__ __align__(16) float sh[2][4][DD];
    int tid = threadIdx.x;
    int g = tid >> 6;
    int j = tid & 63;

    u64 w2[32];
#pragma unroll
    for (int k = 0; k < 32; k += 2) {
        ulonglong2 a = *(const ulonglong2*)&W[j * DD + k * 2];
        w2[k] = a.x;
        w2[k + 1] = a.y;
    }
    float bj = b[j];

    int stride = gridDim.x * 4;
    int i0 = blockIdx.x * 4 + g;
    float hv = (i0 < n) ? x[i0 * DD + j] : 0.f;
    int buf = 0;
    for (int base = blockIdx.x * 4; base < n; base += stride) {
        int i = base + g;
        sh[buf][g][j] = hv;
        __syncthreads();
        int inx = i + stride;
        hv = (inx < n) ? x[inx * DD + j] : 0.f;
        if (i < n) {
            const ulonglong2* h2 = (const ulonglong2*)sh[buf][g];
            u64 acc0 = 0ULL, acc1 = 0ULL;
#pragma unroll
            for (int k4 = 0; k4 < 16; k4++) {
                ulonglong2 H = h2[k4];
                acc0 = fma2(H.x, w2[2 * k4], acc0);
                acc1 = fma2(H.y, w2[2 * k4 + 1], acc1);
            }
            out[i * DD + j] = (lo32(acc0) + hi32(acc0)) + (lo32(acc1) + hi32(acc1)) + bj;
        }
        buf ^= 1;
    }
    gdep_launch_dependents();
}

// ---------------- dual-output transform: p = h@Wl^T, q = h@Wr^T + bl ----------------
// 8 nodes per block-iteration; each thread computes col j for 2 nodes.
__global__ __launch_bounds__(256, 1) void k_gemmPQ(
    const float* __restrict__ h,
    const float* __restrict__ Wl, const float* __restrict__ Wr,
    const float* __restrict__ bl,
    float* __restrict__ p, float* __restrict__ q, int n) {
    __shared__ __align__(16) float sh[2][8][DD];
    gdep_wait();
    int tid = threadIdx.x;
    int g = tid >> 6;       // 0..3
    int j = tid & 63;

    u64 wl2[32], wr2[32];
#pragma unroll
    for (int k = 0; k < 32; k += 2) {
        ulonglong2 a = *(const ulonglong2*)&Wl[j * DD + k * 2];
        wl2[k] = a.x; wl2[k + 1] = a.y;
        ulonglong2 c = *(const ulonglong2*)&Wr[j * DD + k * 2];
        wr2[k] = c.x; wr2[k + 1] = c.y;
    }
    float bj = bl[j];

    int stride = gridDim.x * 8;
    int iA0 = blockIdx.x * 8 + g;
    int iB0 = iA0 + 4;
    float hvA = (iA0 < n) ? h[iA0 * DD + j] : 0.f;
    float hvB = (iB0 < n) ? h[iB0 * DD + j] : 0.f;
    int buf = 0;
    for (int base = blockIdx.x * 8; base < n; base += stride) {
        int iA = base + g;
        int iB = iA + 4;
        sh[buf][g][j] = hvA;
        sh[buf][g + 4][j] = hvB;
        __syncthreads();
        int nA = iA + stride, nB = iB + stride;
        hvA = (nA < n) ? h[nA * DD + j] : 0.f;
        hvB = (nB < n) ? h[nB * DD + j] : 0.f;

        const ulonglong2* hA = (const ulonglong2*)sh[buf][g];
        const ulonglong2* hB = (const ulonglong2*)sh[buf][g + 4];
        u64 pA0 = 0ULL, pA1 = 0ULL, qA0 = 0ULL, qA1 = 0ULL;
        u64 pB0 = 0ULL, pB1 = 0ULL, qB0 = 0ULL, qB1 = 0ULL;
#pragma unroll
        for (int k4 = 0; k4 < 16; k4++) {
            ulonglong2 Ha = hA[k4];
            ulonglong2 Hb = hB[k4];
            u64 wlo = wl2[2 * k4], whi = wl2[2 * k4 + 1];
            u64 rlo = wr2[2 * k4], rhi = wr2[2 * k4 + 1];
            pA0 = fma2(Ha.x, wlo, pA0);
            pA1 = fma2(Ha.y, whi, pA1);
            qA0 = fma2(Ha.x, rlo, qA0);
            qA1 = fma2(Ha.y, rhi, qA1);
            pB0 = fma2(Hb.x, wlo, pB0);
            pB1 = fma2(Hb.y, whi, pB1);
            qB0 = fma2(Hb.x, rlo, qB0);
            qB1 = fma2(Hb.y, rhi, qB1);
        }
        if (iA < n) {
            p[iA * DD + j] = (lo32(pA0) + hi32(pA0)) + (lo32(pA1) + hi32(pA1));
            q[iA * DD + j] = (lo32(qA0) + hi32(qA0)) + (lo32(qA1) + hi32(qA1)) + bj;
        }
        if (iB < n) {
            p[iB * DD + j] = (lo32(pB0) + hi32(pB0)) + (lo32(pB1) + hi32(pB1));
            q[iB * DD + j] = (lo32(qB0) + hi32(qB0)) + (lo32(qB1) + hi32(qB1)) + bj;
        }
        buf ^= 1;
        __syncthreads();
    }
    gdep_launch_dependents();
}

// ---------------- edge dot product (warp per edge, f32x2 lanes) ----------------
__global__ __launch_bounds__(256) void k_edge(
    const float* __restrict__ h, const int* __restrict__ ea,
    const int* __restrict__ eb, float* __restrict__ out, int E) {
    gdep_wait();
    int w = (blockIdx.x * blockDim.x + threadIdx.x) >> 5;
    int lane = threadIdx.x & 31;
    if (w >= E) return;
    int a = ea[w];
    int b = eb[w];
    ulonglong2 va = ((const ulonglong2*)(h + a * DD))[lane >> 1];
    ulonglong2 vb = ((const ulonglong2*)(h + b * DD))[lane >> 1];
    u64 acc = mul2((lane & 1) ? va.y : va.x, (lane & 1) ? vb.y : vb.x);
    float p = lo32(acc) + hi32(acc);
#pragma unroll
    for (int o = 16; o > 0; o >>= 1) p += __shfl_down_sync(0xffffffffu, p, o);
    if (lane == 0) out[w] = p;
}

// ---------------- PDL launch helper ----------------
#define PDL_LAUNCH(kern, grid_, block_, strm_, ...)                              \
    do {                                                                         \
        cudaLaunchConfig_t cfg_ = {};                                            \
        cfg_.gridDim = dim3(grid_);                                              \
        cfg_.blockDim = dim3(block_);                                            \
        cfg_.dynamicSmemBytes = 0;                                               \
        cfg_.stream = (strm_);                                                   \
        cudaLaunchAttribute at_[1];                                              \
        at_[0].id = cudaLaunchAttributeProgrammaticStreamSerialization;          \
        at_[0].val.programmaticStreamSerializationAllowed = 1;                   \
        cfg_.attrs = at_;                                                        \
        cfg_.numAttrs = 1;                                                       \
        cudaLaunchKernelEx(&cfg_, kern, __VA_ARGS__);                            \
    } while (0)

// ---------------- launch ----------------
static cudaStream_t s_side = nullptr;
static cudaEvent_t  s_evF = nullptr;
static cudaEvent_t  s_evPQ = nullptr;

extern "C" void kernel_launch(void* const* d_in, const int* in_sizes, int n_in,
                              void* d_out, int out_size) {
    const float* x     = (const float*)d_in[0];
    const int*   ei    = (const int*)d_in[1];
    const int*   eli   = (const int*)d_in[2];
    const float* W_lin = (const float*)d_in[3];
    const float* b_lin = (const float*)d_in[4];
    const float* Wl1   = (const float*)d_in[5];
    const float* bl1   = (const float*)d_in[6];
    const float* Wr1   = (const float*)d_in[7];
    const float* Wl2   = (const float*)d_in[8];
    const float* bl2   = (const float*)d_in[9];
    const float* Wr2   = (const float*)d_in[10];

    int N  = in_sizes[0] / DD;      // 100000
    int E  = in_sizes[1] / 2;       // 1000000
    int EL = in_sizes[2] / 2;       // 200000

    const int* src = ei;            // edge_index[0] = source
    const int* dst = ei + E;        // edge_index[1] = target
    const int* ea  = eli;
    const int* eb  = eli + EL;

    float *h0, *h1, *p, *q;
    int *deg, *rowptr, *cursor, *col;
    u64 *state;
    cudaGetSymbolAddress((void**)&h0, g_h0);
    cudaGetSymbolAddress((void**)&h1, g_h1);
    cudaGetSymbolAddress((void**)&p, g_p);
    cudaGetSymbolAddress((void**)&q, g_q);
    cudaGetSymbolAddress((void**)&deg, g_deg);
    cudaGetSymbolAddress((void**)&rowptr, g_rowptr);
    cudaGetSymbolAddress((void**)&cursor, g_cursor);
    cudaGetSymbolAddress((void**)&col, g_col);
    cudaGetSymbolAddress((void**)&state, g_scan_state);

    float* preds = (float*)d_out;

    // One-time stream/event creation (first call is the uncaptured correctness
    // run, so no resource creation happens during graph capture).
    if (s_side == nullptr) {
        cudaStreamCreateWithFlags(&s_side, cudaStreamNonBlocking);
        cudaEventCreateWithFlags(&s_evF, cudaEventDisableTiming);
        cudaEventCreateWithFlags(&s_evPQ, cudaEventDisableTiming);
    }

    int nblk = (N + SCAN_CHUNK - 1) / SCAN_CHUNK;   // 196 <= 256
    cudaStream_t main0 = 0;

    // Side stream: node_lin then layer-1 transform (p,q) — independent of the
    // CSR build, fully overlapped with it. gemmPQ1 PDL-chained behind lin.
    cudaEventRecord(s_evF, main0);
    cudaStreamWaitEvent(s_side, s_evF, 0);
    k_lin<<<296, 256, 0, s_side>>>(x, W_lin, b_lin, h0, N);
    PDL_LAUNCH(k_gemmPQ, 148, 256, s_side, (const float*)h0, Wl1, Wr1, bl1, p, q, N);
    cudaEventRecord(s_evPQ, s_side);

    // Main stream: CSR build. scan/scatter PDL-chained.
    cudaMemsetAsync(deg, 0, N * sizeof(int), main0);
    cudaMemsetAsync(state, 0, 256 * sizeof(u64), main0);
    k_hist<<<1024, 256, 0, main0>>>(dst, deg, E);
    PDL_LAUNCH(k_scan, nblk, 256, main0, (const int*)deg, rowptr, cursor, state, N, nblk);
    PDL_LAUNCH(k_scatter, 2048, 256, main0, src, dst, cursor, col, E);

    // Join: aggregation needs p,q and CSR.
    cudaStreamWaitEvent(main0, s_evPQ, 0);

    int agg_blocks = (N * 16 + 255) / 256;

    // layer 1: h1 = relu(agg(p) + q)
    PDL_LAUNCH(k_aggc, agg_blocks, 256, main0, (const float*)p, (const float*)q,
               (const int*)rowptr, (const int*)col, h1, N, 1);
    // layer 2 transform: p,q from h1
    PDL_LAUNCH(k_gemmPQ, 148, 256, main0, (const float*)h1, Wl2, Wr2, bl2, p, q, N);
    // layer 2 combine: h0 = agg(p) + q
    PDL_LAUNCH(k_aggc, agg_blocks, 256, main0, (const float*)p, (const float*)q,
               (const int*)rowptr, (const int*)col, h0, N, 0);

    // edge classifier
    int blocks = (EL * 32 + 255) / 256;
    PDL_LAUNCH(k_edge, blocks, 256, main0, (const float*)h0, ea, eb, preds, EL);
}